// round 17
// baseline (speedup 1.0000x reference)
#include <cuda_runtime.h>
#include <cuda_fp16.h>
#include <math.h>
#include <stdint.h>

#define N_OBJ 2048
#define FDIM  2048
#define HDIM  1024
#define G6    6144          // 6*HDIM
#define NALL  7168          // 6*HDIM + HDIM (fused XG|PX width)
#define KCAT  2048          // 2*HDIM
#define NPAIR 32            // (2048/64) BK64 pairs total

// plane strides (elements)
#define PS_F  ((size_t)N_OBJ * FDIM)
#define PS_WA ((size_t)NALL * FDIM)
#define PS_WC ((size_t)G6 * KCAT)
#define PS_H  ((size_t)(N_OBJ + 1) * HDIM)

#define NCTA_PERSIST 296

// ---------------- scratch (static device globals; no allocation) -------------
__device__ float g_XGP[(size_t)N_OBJ * NALL];        // [XG | PX] fused
__device__ float g_biaslr[G6];
__device__ float g_biasA[NALL];                      // b_iox | b_px
__device__ float g_C[(size_t)(N_OBJ + 1) * HDIM];
__device__ float g_H[(size_t)(N_OBJ + 1) * HDIM];
__device__ float g_Gh[(size_t)2048 * G6];            // level split-K slabs

// fp16 operand planes (single plane each side)
__device__ __half g_Fe [PS_F];                       // features
__device__ __half g_WAe[PS_WA];                      // [w_iox; w_px]
__device__ __half g_Wce[PS_WC];                      // [Wl | Wr]
__device__ __half g_He [PS_H];                       // hidden

// grid-barrier state
__device__ unsigned g_bar_count = 0;
__device__ unsigned g_bar_gen = 0;

// ---------------- helpers ----------------------------------------------------
__device__ __forceinline__ uint32_t smem_to_u32(const void* p) {
    uint32_t a;
    asm("{ .reg .u64 t; cvta.to.shared.u64 t, %1; cvt.u32.u64 %0, t; }" : "=r"(a) : "l"(p));
    return a;
}
__device__ __forceinline__ void ldmx4(uint32_t* d, uint32_t addr) {
    asm volatile("ldmatrix.sync.aligned.m8n8.x4.shared.b16 {%0,%1,%2,%3}, [%4];"
                 : "=r"(d[0]), "=r"(d[1]), "=r"(d[2]), "=r"(d[3]) : "r"(addr));
}
__device__ __forceinline__ void mma_f16(float* c, const uint32_t* a, const uint32_t* b) {
    asm volatile("mma.sync.aligned.m16n8k16.row.col.f32.f16.f16.f32 "
                 "{%0,%1,%2,%3}, {%4,%5,%6,%7}, {%8,%9}, {%0,%1,%2,%3};"
                 : "+f"(c[0]), "+f"(c[1]), "+f"(c[2]), "+f"(c[3])
                 : "r"(a[0]), "r"(a[1]), "r"(a[2]), "r"(a[3]), "r"(b[0]), "r"(b[1]));
}
__device__ __forceinline__ void cpasync16(uint32_t dst, const void* src) {
    asm volatile("cp.async.cg.shared.global [%0], [%1], 16;" :: "r"(dst), "l"(src));
}
__device__ __forceinline__ uint32_t swz(int r, int x) {
    return (uint32_t)(r * 64 + ((x ^ ((r >> 1) & 3)) << 4));
}
__device__ __forceinline__ float sigm(float x) { return 1.f / (1.f + expf(-x)); }

// ---------------- mma tile worker: BM=128, BN=128, BK64 x cnt ----------------
// Computes C[row0:+128, col0:+128] (+bias) = A @ B^T over pairs [p0, p0+cnt).
// A, B: fp16 planes, row stride 2048. Uses 3x32KB smem stages. 256 threads.
__device__ void mma_tile128(const __half* __restrict__ A, const __half* __restrict__ B,
                            const float* __restrict__ bias, float* __restrict__ C,
                            int M, int N, int row0, int col0, int p0, int cnt,
                            uint32_t sb)
{
    constexpr int ATB = 8192, SUB = 16384, STAGE = 32768;
    const int tid = threadIdx.x, lane = tid & 31, warp = tid >> 5;
    const int wr_ = warp >> 2, wc_ = warp & 3;
    const int lrow = ((lane >> 3) & 1) * 8 + (lane & 7);
    const int lcol = lane >> 4;
    const int r_op0 = tid >> 2,         ch0 = tid & 3;
    const int r_op1 = (tid + 256) >> 2, ch1 = tid & 3;

    float acc[4][4][4];
#pragma unroll
    for (int a = 0; a < 4; a++)
#pragma unroll
        for (int b = 0; b < 4; b++)
#pragma unroll
            for (int t = 0; t < 4; t++) acc[a][b][t] = 0.f;

    auto load_sub = [&](int c, uint32_t off) {
        const __half* Ab = A + (size_t)c * 32;
        const __half* Bb = B + (size_t)c * 32;
        uint32_t sA = sb + off, sBm = sA + ATB;
        cpasync16(sA + swz(r_op0, ch0), Ab + (size_t)(row0 + r_op0) * 2048 + ch0 * 8);
        cpasync16(sA + swz(r_op1, ch1), Ab + (size_t)(row0 + r_op1) * 2048 + ch1 * 8);
        cpasync16(sBm + swz(r_op0, ch0), Bb + (size_t)(col0 + r_op0) * 2048 + ch0 * 8);
        cpasync16(sBm + swz(r_op1, ch1), Bb + (size_t)(col0 + r_op1) * 2048 + ch1 * 8);
    };
    auto load_pair = [&](int p, int st) {
        load_sub(2 * p,     (uint32_t)(st * STAGE));
        load_sub(2 * p + 1, (uint32_t)(st * STAGE + SUB));
        asm volatile("cp.async.commit_group;" ::: "memory");
    };
    auto ldfrag = [&](int st, int kk, uint32_t af[4][4], uint32_t bq[2][4]) {
        uint32_t sA = sb + st * STAGE + (kk >> 1) * SUB;
        uint32_t sBm = sA + ATB;
        int kl = (kk & 1) * 2 + lcol;
#pragma unroll
        for (int mf = 0; mf < 4; mf++) {
            int r = wr_ * 64 + mf * 16 + lrow;
            ldmx4(af[mf], sA + swz(r, kl));
        }
#pragma unroll
        for (int bh = 0; bh < 2; bh++) {
            int r = wc_ * 32 + bh * 16 + lrow;
            ldmx4(bq[bh], sBm + swz(r, kl));
        }
    };

    load_pair(p0, 0);
    if (cnt > 1) load_pair(p0 + 1, 1);

    uint32_t fA[2][4][4], fB[2][2][4];

    for (int i = 0; i < cnt; i++) {
        int st = i % 3;
        if (i + 2 < cnt) {
            asm volatile("cp.async.wait_group 1;" ::: "memory");
        } else {
            asm volatile("cp.async.wait_group 0;" ::: "memory");
        }
        __syncthreads();
        if (i + 2 < cnt) load_pair(p0 + i + 2, (i + 2) % 3);

        ldfrag(st, 0, fA[0], fB[0]);
#pragma unroll
        for (int kk = 0; kk < 4; kk++) {
            if (kk < 3) ldfrag(st, kk + 1, fA[(kk + 1) & 1], fB[(kk + 1) & 1]);
            uint32_t (*af)[4] = fA[kk & 1];
            uint32_t (*bq)[4] = fB[kk & 1];
#pragma unroll
            for (int mf = 0; mf < 4; mf++)
#pragma unroll
                for (int nf = 0; nf < 4; nf++) {
                    uint32_t b2[2] = { bq[nf >> 1][nf & 1], bq[nf >> 1][2 + (nf & 1)] };
                    mma_f16(acc[mf][nf], af[mf], b2);
                }
        }
    }
    __syncthreads();   // stages free for next tile

#pragma unroll
    for (int mf = 0; mf < 4; mf++) {
#pragma unroll
        for (int nf = 0; nf < 4; nf++) {
            int r  = row0 + wr_ * 64 + mf * 16 + (lane >> 2);
            int cb = col0 + wc_ * 32 + nf * 8 + (lane & 3) * 2;
            float b0 = bias ? bias[cb] : 0.f;
            float b1 = bias ? bias[cb + 1] : 0.f;
            if (r < M) {
                C[(size_t)r * N + cb]     = acc[mf][nf][0] + b0;
                C[(size_t)r * N + cb + 1] = acc[mf][nf][1] + b1;
            }
            if (r + 8 < M) {
                C[(size_t)(r + 8) * N + cb]     = acc[mf][nf][2] + b0;
                C[(size_t)(r + 8) * N + cb + 1] = acc[mf][nf][3] + b1;
            }
        }
    }
}

// ---------------- merged expansion + prep (one launch) -----------------------
__global__ void expand_all_kernel(const float* __restrict__ features,
                                  const float* __restrict__ w_iox,
                                  const float* __restrict__ w_px,
                                  const float* __restrict__ wl,
                                  const float* __restrict__ wr,
                                  const float* __restrict__ bl,
                                  const float* __restrict__ br,
                                  const float* __restrict__ bx,
                                  const float* __restrict__ bp)
{
    const size_t E0 = PS_F;
    const size_t E1 = E0 + (size_t)G6 * FDIM;
    const size_t E2 = E1 + (size_t)HDIM * FDIM;
    const size_t E3 = E2 + PS_WC;
    const size_t E4 = E3 + NALL;                      // bias/sentinel range
    for (size_t i = (size_t)blockIdx.x * 256 + threadIdx.x; i < E4;
         i += (size_t)gridDim.x * 256) {
        if (i < E0) {
            g_Fe[i] = __float2half_rn(features[i]);
        } else if (i < E1) {
            size_t k = i - E0;
            g_WAe[k] = __float2half_rn(w_iox[k]);
        } else if (i < E2) {
            size_t k = i - E1;
            g_WAe[(size_t)G6 * FDIM + k] = __float2half_rn(w_px[k]);
        } else if (i < E3) {
            size_t idx = i - E2;
            size_t j = idx >> 11;
            int k = (int)(idx & (KCAT - 1));
            float w = (k < HDIM) ? wl[j * HDIM + k] : wr[j * HDIM + (k - HDIM)];
            g_Wce[idx] = __float2half_rn(w);
        } else {
            int idx = (int)(i - E3);                  // 0..NALL-1
            if (idx < G6) g_biaslr[idx] = bl[idx] + br[idx];
            g_biasA[idx] = (idx < G6) ? bx[idx] : bp[idx - G6];
            if (idx < HDIM) {
                size_t s = (size_t)N_OBJ * HDIM + idx;
                g_C[s] = 0.f; g_H[s] = 0.f;
                g_He[s] = __float2half_rn(0.f);
            }
        }
    }
}

// ---------------- phase-A GEMM launcher kernel -------------------------------
__global__ __launch_bounds__(256, 2) void gemm_phaseA()
{
    extern __shared__ char smem[];
    const uint32_t sb = smem_to_u32(smem);
    // L2-aware supertiling over 56 x 16 tiles
    const int tiles_n = NALL / 128, tiles_m = N_OBJ / 128;
    int lid = blockIdx.y * tiles_n + blockIdx.x;
    const int GRP = 8;
    int per_group = GRP * tiles_m;
    int grp = lid / per_group, rem = lid - grp * per_group;
    int nt0 = grp * GRP;
    int gn = tiles_n - nt0; if (gn > GRP) gn = GRP;
    int nt = nt0 + rem % gn;
    int mt = rem / gn;
    mma_tile128(g_Fe, g_WAe, g_biasA, g_XGP, N_OBJ, NALL,
                mt * 128, nt * 128, 0, NPAIR, sb);
}

// ---------------- persistent post-phase-A kernel -----------------------------
__device__ __forceinline__ void grid_barrier()
{
    __syncthreads();
    if (threadIdx.x == 0) {
        __threadfence();
        unsigned gen = *((volatile unsigned*)&g_bar_gen);
        unsigned ticket = atomicAdd(&g_bar_count, 1);
        if (ticket == gridDim.x - 1) {
            g_bar_count = 0;
            __threadfence();
            atomicAdd(&g_bar_gen, 1);
        } else {
            while (*((volatile unsigned*)&g_bar_gen) == gen) __nanosleep(64);
        }
        __threadfence();
    }
    __syncthreads();
}

// warp-per-column small GEMM over level (s, M): Gh[m][n] = A @ Wce^T
__device__ void small_gemm_level(int s, int M)
{
    const int warp = threadIdx.x >> 5, lane = threadIdx.x & 31;
    const float* A = g_H + (size_t)(2 * s + 1) * HDIM;
    for (int n = blockIdx.x * 8 + warp; n < G6; n += gridDim.x * 8) {
        float acc[16];
#pragma unroll
        for (int m = 0; m < 16; m++) acc[m] = 0.f;
        const __half* Brow = g_Wce + (size_t)n * KCAT;
        for (int k = lane * 8; k < KCAT; k += 256) {
            uint4 braw = *(const uint4*)(Brow + k);
            float2 b01 = __half22float2(*(__half2*)&braw.x);
            float2 b23 = __half22float2(*(__half2*)&braw.y);
            float2 b45 = __half22float2(*(__half2*)&braw.z);
            float2 b67 = __half22float2(*(__half2*)&braw.w);
#pragma unroll
            for (int m = 0; m < 16; m++) {
                if (m < M) {
                    float4 a0 = *(const float4*)(A + (size_t)m * KCAT + k);
                    float4 a1 = *(const float4*)(A + (size_t)m * KCAT + k + 4);
                    acc[m] += a0.x * b01.x + a0.y * b01.y + a0.z * b23.x + a0.w * b23.y
                            + a1.x * b45.x + a1.y * b45.y + a1.z * b67.x + a1.w * b67.y;
                }
            }
        }
#pragma unroll
        for (int m = 0; m < 16; m++) {
            if (m < M) {
                float v = acc[m];
#pragma unroll
                for (int off = 16; off; off >>= 1) v += __shfl_xor_sync(~0u, v, off);
                if (lane == 0) g_Gh[(size_t)m * G6 + n] = v;
            }
        }
    }
}

// grid-strided pointwise for level (s, M); nparts==0 -> leaves (no Gh)
__device__ void pointwise_level(int s, int M, int nparts, float* __restrict__ out)
{
    for (int idx = blockIdx.x * 256 + threadIdx.x; idx < M * HDIM;
         idx += gridDim.x * 256) {
        int m = idx >> 10;
        int j = idx & (HDIM - 1);
        int n = s + m;
        const float* xg = g_XGP + (size_t)n * NALL;
        float g[6];
#pragma unroll
        for (int t = 0; t < 6; t++) {
            int o = t * HDIM + j;
            float v = xg[o] + g_biaslr[o];
            for (int p = 0; p < nparts; p++)
                v += g_Gh[(size_t)p * ((size_t)M * G6) + (size_t)m * G6 + o];
            g[t] = v;
        }
        float ig = sigm(g[0]), og = sigm(g[1]);
        float fl = sigm(g[2]), fr = sigm(g[3]);
        float u  = tanhf(g[4]), rr = sigm(g[5]);

        int l = 2 * n + 1; if (l > N_OBJ) l = N_OBJ;
        int r = 2 * n + 2; if (r > N_OBJ) r = N_OBJ;

        float c = ig * u + fl * g_C[(size_t)l * HDIM + j]
                         + fr * g_C[(size_t)r * HDIM + j];
        float h = og * tanhf(c);
        float hf = rr * h + (1.f - rr) * xg[G6 + j];
        size_t o = (size_t)n * HDIM + j;
        g_C[o] = c;
        g_H[o] = hf;
        out[o] = hf;
        g_He[o] = __float2half_rn(hf);
    }
}

__global__ __launch_bounds__(256, 2) void persist_kernel(float* __restrict__ out)
{
    extern __shared__ char smem[];
    const uint32_t sb = smem_to_u32(smem);

    // ---- leaves (nodes 1024..2047) ----
    pointwise_level(1024, 1024, 0, out);
    grid_barrier();

    // ---- node 1023 (children: H row 2047 + sentinel 2048) ----
    small_gemm_level(1023, 1);
    grid_barrier();
    pointwise_level(1023, 1, 1, out);
    grid_barrier();

    // ---- mma levels ----
    const int sv[5]  = {511, 255, 127, 63, 31};
    const int Mv[5]  = {512, 256, 128, 64, 32};
    const int KSv[5] = {3, 3, 6, 6, 6};
    for (int li = 0; li < 5; li++) {
        const int s = sv[li], M = Mv[li], KS = KSv[li];
        const int Mtiles = (M + 127) / 128;
        const int ppp = (NPAIR + KS - 1) / KS;
        const int njobs = 48 * Mtiles * KS;
        const __half* A = g_He + (size_t)(2 * s + 1) * HDIM;
        for (int job = blockIdx.x; job < njobs; job += gridDim.x) {
            int part = job / (48 * Mtiles);
            int rem  = job % (48 * Mtiles);
            int mt = rem / 48, nt = rem % 48;
            int p0 = part * ppp;
            int cnt = NPAIR - p0; if (cnt > ppp) cnt = ppp;
            mma_tile128(A, g_Wce, nullptr,
                        g_Gh + (size_t)part * M * G6, M, G6,
                        mt * 128, nt * 128, p0, cnt, sb);
        }
        grid_barrier();
        pointwise_level(s, M, KS, out);
        grid_barrier();
    }

    // ---- tail levels M=16..1 ----
    const int sv2[5] = {15, 7, 3, 1, 0};
    const int Mv2[5] = {16, 8, 4, 2, 1};
    for (int li = 0; li < 5; li++) {
        small_gemm_level(sv2[li], Mv2[li]);
        grid_barrier();
        pointwise_level(sv2[li], Mv2[li], 1, out);
        grid_barrier();
    }
}

// ---------------- launcher ---------------------------------------------------
extern "C" void kernel_launch(void* const* d_in, const int* in_sizes, int n_in,
                              void* d_out, int out_size)
{
    const float* features = (const float*)d_in[0];
    const float* w_iox    = (const float*)d_in[1];
    const float* b_iox    = (const float*)d_in[2];
    const float* w_l      = (const float*)d_in[3];
    const float* b_l      = (const float*)d_in[4];
    const float* w_r      = (const float*)d_in[5];
    const float* b_r      = (const float*)d_in[6];
    const float* w_px     = (const float*)d_in[7];
    const float* b_px     = (const float*)d_in[8];
    float* out = (float*)d_out;

    const int SMEM_TC = 3 * 32768;
    cudaFuncSetAttribute(gemm_phaseA, cudaFuncAttributeMaxDynamicSharedMemorySize, SMEM_TC);
    cudaFuncSetAttribute(persist_kernel, cudaFuncAttributeMaxDynamicSharedMemorySize, SMEM_TC);

    // 1) all operand expansion + biases + sentinels (one launch)
    expand_all_kernel<<<4096, 256>>>(features, w_iox, w_px, w_l, w_r,
                                     b_l, b_r, b_iox, b_px);

    // 2) phase A: fused [XG | PX] GEMM, N = 7168
    gemm_phaseA<<<dim3(NALL / 128, N_OBJ / 128), 256, SMEM_TC>>>();

    // 3) everything else: one persistent kernel
    persist_kernel<<<NCTA_PERSIST, 256, SMEM_TC>>>(out);
}